// round 3
// baseline (speedup 1.0000x reference)
#include <cuda_runtime.h>
#include <math.h>

#define BB   64
#define NN   64
#define DD   256
#define LAPD 16
#define MM   2016          // N*(N-1)/2
#define SEQ  2081          // 1 + N + M

// Scratch (no allocation allowed in kernel_launch)
__device__ float g_proju[BB * NN * DD];   // 4 MB (C folded in)
__device__ float g_projv[BB * NN * DD];   // 4 MB
__device__ unsigned short g_edge[BB * MM];
__device__ int g_count[BB];

// Map linear upper-tri index m -> (i, j), i<j, row-major (triu_indices order)
__device__ __forceinline__ void m2ij(int m, int& i, int& j) {
    int ii = (int)((127.0 - sqrt(16129.0 - 8.0 * (double)m)) * 0.5);
    if (ii < 0) ii = 0;
    if (ii > 62) ii = 62;
    while (ii < 62 && (ii + 1) * (127 - (ii + 1)) / 2 <= m) ii++;
    while (ii > 0 && ii * (127 - ii) / 2 > m) ii--;
    i = ii;
    j = ii + 1 + (m - ii * (127 - ii) / 2);
}

// Fused: blocks [0,256) = proj; blocks [256,320) = scan + full edge mask tail.
__global__ void fused_proj_scan(const float* __restrict__ node_feats,
                                const float* __restrict__ eigvec,
                                const float* __restrict__ W_lap,
                                const float* __restrict__ W_edge,
                                const float* __restrict__ b_edge,
                                const float* __restrict__ type_embed,
                                const float* __restrict__ graph_tok,
                                const int*  __restrict__ adj,
                                float* __restrict__ out) {
    __shared__ float sh[256];
    int tid = threadIdx.x;

    if (blockIdx.x < 256) {
        // ---------------- proj ----------------
        int b  = blockIdx.x >> 2;
        int g  = blockIdx.x & 3;
        int n0 = g * 16;
        int d  = tid;

        float wl[LAPD], wu[LAPD], wv[LAPD];
#pragma unroll
        for (int l = 0; l < LAPD; l++) {
            wl[l] = __ldg(&W_lap[l * DD + d]);
            wu[l] = __ldg(&W_edge[(1 + l) * DD + d]);
            wv[l] = __ldg(&W_edge[(1 + LAPD + l) * DD + d]);
        }
        float Cd = __ldg(&W_edge[d]) + __ldg(&b_edge[d]) + __ldg(&type_embed[DD + d]);

        sh[tid] = eigvec[(size_t)(b * NN + n0) * LAPD + tid];
        __syncthreads();

#pragma unroll 4
        for (int n = 0; n < 16; n++) {
            int node = b * NN + n0 + n;
            float nt = node_feats[(size_t)node * DD + d];
            float pu = 0.f, pv = 0.f;
#pragma unroll
            for (int l = 0; l < LAPD; l++) {
                float ev = sh[n * LAPD + l];
                nt += ev * wl[l];
                pu += ev * wu[l];
                pv += ev * wv[l];
            }
            __stcs(&out[((size_t)b * SEQ + 1 + n0 + n) * DD + d], nt);
            g_proju[(size_t)node * DD + d] = pu + Cd;
            g_projv[(size_t)node * DD + d] = pv;
        }

        if (g == 0) {
            __stcs(&out[(size_t)b * SEQ * DD + d], graph_tok[d]);
            float* maskf = out + (size_t)BB * SEQ * DD;
            if (d < 1 + NN) maskf[(size_t)b * SEQ + d] = 0.f;
        }
    } else {
        // ---------------- scan + mask tail ----------------
        int b = blockIdx.x - 256;
        int* s = (int*)sh;
        const int* adjb = adj + (size_t)b * NN * NN;

        int m0 = tid * 8;
        int i, j;
        int v[8], ij[8];
        int local = 0;
        if (m0 < MM) {
            m2ij(m0, i, j);
#pragma unroll
            for (int q = 0; q < 8; q++) {
                int m = m0 + q;
                int val = 0, pack = 0;
                if (m < MM) {
                    pack = (i << 6) | j;
                    val = adjb[i * NN + j] > 0;
                    j++;
                    if (j == NN) { i++; j = i + 1; }
                }
                v[q] = val; ij[q] = pack;
                local += val;
            }
        } else {
#pragma unroll
            for (int q = 0; q < 8; q++) { v[q] = 0; ij[q] = 0; }
        }

        s[tid] = local;
        __syncthreads();
#pragma unroll
        for (int off = 1; off < 256; off <<= 1) {
            int add = (tid >= off) ? s[tid - off] : 0;
            __syncthreads();
            s[tid] += add;
            __syncthreads();
        }
        int pos = s[tid] - local;
#pragma unroll
        for (int q = 0; q < 8; q++) {
            if (v[q]) g_edge[b * MM + pos++] = (unsigned short)ij[q];
        }
        int total = s[255];
        if (tid == 255) g_count[b] = total;

        // contiguous edge mask tail for this batch
        float* maskf = out + (size_t)BB * SEQ * DD + (size_t)b * SEQ + 1 + NN;
#pragma unroll
        for (int k = tid; k < MM; k += 256)
            maskf[k] = (k < total) ? 0.f : 1.f;
    }
}

// Edge kernel: grid (126, 64). 16 rows/block, 4 rows/thread, indices via smem,
// unconditional gathers (MLP=8), streaming float4 stores.
__global__ void edge_kernel(float* __restrict__ out) {
    int b    = blockIdx.y;
    int r0   = blockIdx.x << 4;           // 16 rows per block
    int tid  = threadIdx.x;
    int rg   = tid >> 6;                  // 0..3
    int lane = tid & 63;

    __shared__ int sIdx[16];
    if (tid < 16) {
        int k = r0 + tid;
        int K = g_count[b];
        sIdx[tid] = (k < K) ? (int)g_edge[b * MM + k] : -1;
    }
    __syncthreads();

    const float4* pu = (const float4*)(g_proju + (size_t)b * NN * DD);
    const float4* pv = (const float4*)(g_projv + (size_t)b * NN * DD);

    int p[4];
    float4 a[4], c[4];
#pragma unroll
    for (int q = 0; q < 4; q++) {
        p[q] = sIdx[rg + (q << 2)];
        int ps = p[q] < 0 ? 0 : p[q];
        a[q] = __ldg(&pu[((ps >> 6) << 6) + lane]);
        c[q] = __ldg(&pv[((ps & 63) << 6) + lane]);
    }

    float4* orow = (float4*)(out + ((size_t)b * SEQ + 1 + NN + r0) * DD);
#pragma unroll
    for (int q = 0; q < 4; q++) {
        float4 v = make_float4(0.f, 0.f, 0.f, 0.f);
        if (p[q] >= 0)
            v = make_float4(a[q].x + c[q].x, a[q].y + c[q].y,
                            a[q].z + c[q].z, a[q].w + c[q].w);
        __stcs(&orow[((rg + (q << 2)) << 6) + lane], v);
    }
}

extern "C" void kernel_launch(void* const* d_in, const int* in_sizes, int n_in,
                              void* d_out, int out_size) {
    const int*   adj        = (const int*)d_in[0];
    const float* node_feats = (const float*)d_in[1];
    const float* eigvec     = (const float*)d_in[2];
    const float* W_lap      = (const float*)d_in[3];
    const float* W_edge     = (const float*)d_in[4];
    const float* b_edge     = (const float*)d_in[5];
    const float* type_embed = (const float*)d_in[6];
    const float* graph_tok  = (const float*)d_in[7];
    float* out = (float*)d_out;

    fused_proj_scan<<<320, 256>>>(node_feats, eigvec, W_lap, W_edge, b_edge,
                                  type_embed, graph_tok, adj, out);
    edge_kernel<<<dim3(126, 64), 256>>>(out);
}